// round 9
// baseline (speedup 1.0000x reference)
#include <cuda_runtime.h>
#include <cuda_bf16.h>
#include <stdint.h>
#include <math.h>

#define Bb   8
#define Nn   1024
#define INc  256
#define AXc  512
#define Dd   768
#define OUTc 256
#define ALPHA 0.2f
#define NEGV  -9.0e15f

typedef __nv_bfloat16 bf16;

// ---------------- scratch (static device globals; no allocation) ----------------
__device__ float g_M[OUTc * INc];        // fc_w[:, :256] @ WQ_w
__device__ float g_v1[INc], g_v2[INc];
__device__ float g_zb[OUTc];
__device__ float g_c[2];
__device__ __align__(16) float g_f1[Bb * Nn];
__device__ __align__(16) float g_f2[Bb * Nn];

__device__ __align__(16) bf16 g_att_h[(size_t)Bb * Nn * Nn];   // att hi/lo, [b][i][j]
__device__ __align__(16) bf16 g_att_l[(size_t)Bb * Nn * Nn];
__device__ __align__(16) bf16 g_X_h[(size_t)Bb * Nn * Dd];     // Xcat^T, [b][n][k]
__device__ __align__(16) bf16 g_X_l[(size_t)Bb * Nn * Dd];
__device__ __align__(16) bf16 g_W_h[OUTc * Dd];                // Wcat, [o][k]
__device__ __align__(16) bf16 g_W_l[OUTc * Dd];
__device__ __align__(16) bf16 g_z_h[(size_t)Bb * OUTc * Nn];   // z^T,  [b][o][n]
__device__ __align__(16) bf16 g_z_l[(size_t)Bb * OUTc * Nn];

__device__ __forceinline__ void split_bf16(float v, bf16& h, bf16& l) {
    h = __float2bfloat16(v);
    l = __float2bfloat16(v - __bfloat162float(h));
}

__device__ __forceinline__ uint32_t pack2(bf16 a, bf16 b) {
    return (uint32_t)__bfloat16_as_ushort(a) | ((uint32_t)__bfloat16_as_ushort(b) << 16);
}

__device__ __forceinline__ void ldsm4(uint32_t& r0, uint32_t& r1, uint32_t& r2,
                                      uint32_t& r3, uint32_t addr) {
    asm volatile(
        "ldmatrix.sync.aligned.m8n8.x4.shared.b16 {%0,%1,%2,%3}, [%4];"
        : "=r"(r0), "=r"(r1), "=r"(r2), "=r"(r3) : "r"(addr));
}

__device__ __forceinline__ void mma16816(float& c0, float& c1, float& c2, float& c3,
                                         uint32_t a0, uint32_t a1, uint32_t a2, uint32_t a3,
                                         uint32_t b0, uint32_t b1) {
    asm volatile(
        "mma.sync.aligned.m16n8k16.row.col.f32.bf16.bf16.f32 "
        "{%0,%1,%2,%3},{%4,%5,%6,%7},{%8,%9},{%0,%1,%2,%3};"
        : "+f"(c0), "+f"(c1), "+f"(c2), "+f"(c3)
        : "r"(a0), "r"(a1), "r"(a2), "r"(a3), "r"(b0), "r"(b1));
}

__device__ __forceinline__ void cp16(uint32_t dst, const void* src) {
    asm volatile("cp.async.cg.shared.global [%0], [%1], 16;" :: "r"(dst), "l"(src));
}
__device__ __forceinline__ void cp_commit() {
    asm volatile("cp.async.commit_group;");
}
__device__ __forceinline__ void cp_wait1() {
    asm volatile("cp.async.wait_group 1;");
}

// ---------------- prep ----------------
__global__ void prep_M(const float* __restrict__ fc_w, const float* __restrict__ WQ) {
    int o = blockIdx.x, k = threadIdx.x;
    const float* fr = fc_w + o * Dd;
    float s = 0.f;
    for (int t = 0; t < INc; ++t) s += fr[t] * WQ[t * INc + k];
    g_M[o * INc + k] = s;
}

__global__ void prep_small(const float* __restrict__ WQ, const float* __restrict__ WQb,
                           const float* __restrict__ a, const float* __restrict__ fc_w) {
    int t = threadIdx.x;
    float s1 = 0.f, s2 = 0.f;
    for (int r = 0; r < INc; ++r) {
        float w = WQ[r * INc + t];
        s1 += w * a[r];
        s2 += w * a[Dd + r];
    }
    g_v1[t] = s1; g_v2[t] = s2;
    const float* fr = fc_w + t * Dd;
    float z = 0.f;
    for (int r = 0; r < INc; ++r) z += WQb[r] * fr[r];
    g_zb[t] = z;
    __shared__ float r1[256], r2[256];
    r1[t] = WQb[t] * a[t];
    r2[t] = WQb[t] * a[Dd + t];
    __syncthreads();
    for (int st = 128; st > 0; st >>= 1) {
        if (t < st) { r1[t] += r1[t + st]; r2[t] += r2[t + st]; }
        __syncthreads();
    }
    if (t == 0) { g_c[0] = r1[0]; g_c[1] = r2[0]; }
}

__global__ void conv_w(const float* __restrict__ fc_w) {
    int idx = blockIdx.x * 256 + threadIdx.x;
    int o = idx / Dd, k = idx - o * Dd;
    float v = (k < INc) ? g_M[o * INc + k] : fc_w[o * Dd + k];
    bf16 h, l; split_bf16(v, h, l);
    g_W_h[idx] = h; g_W_l[idx] = l;
}

// Xcat^T: [b][n][k] bf16 hi/lo, tiled transpose
__global__ __launch_bounds__(256) void conv_x(const float* __restrict__ x,
                                              const float* __restrict__ ax) {
    __shared__ float tile[32][33];
    int b = blockIdx.z;
    int k0 = blockIdx.x * 32, n0 = blockIdx.y * 32;
    int t = threadIdx.x;
    int tn = t & 31, tk = t >> 5;
    #pragma unroll
    for (int u = 0; u < 4; ++u) {
        int kk = k0 + tk + 8 * u;
        float vv = (kk < INc) ? x[((size_t)b * INc + kk) * Nn + n0 + tn]
                              : ax[((size_t)b * AXc + (kk - INc)) * Nn + n0 + tn];
        tile[tk + 8 * u][tn] = vv;
    }
    __syncthreads();
    int wn = t >> 3, wk = (t & 7) * 4;
    bf16 h[4], l[4];
    #pragma unroll
    for (int u = 0; u < 4; ++u) split_bf16(tile[wk + u][wn], h[u], l[u]);
    size_t idx = ((size_t)b * Nn + n0 + wn) * Dd + k0 + wk;
    *(uint2*)(g_X_h + idx) = make_uint2(pack2(h[0], h[1]), pack2(h[2], h[3]));
    *(uint2*)(g_X_l + idx) = make_uint2(pack2(l[0], l[1]), pack2(l[2], l[3]));
}

// ---------------- f1/f2 ----------------
__global__ void f_kernel(const float* __restrict__ x, const float* __restrict__ ax,
                         const float* __restrict__ a) {
    int b  = blockIdx.y;
    int n  = blockIdx.x * 32 + threadIdx.x;
    int ty = threadIdx.y;
    const float* xb  = x  + (size_t)b * INc * Nn;
    const float* axb = ax + (size_t)b * AXc * Nn;
    float s1 = 0.f, s2 = 0.f;
    for (int k = ty; k < INc; k += 8) {
        float v = xb[k * Nn + n];
        s1 += v * g_v1[k];
        s2 += v * g_v2[k];
    }
    for (int c = ty; c < AXc; c += 8) {
        float v = axb[c * Nn + n];
        s1 += v * a[INc + c];
        s2 += v * a[Dd + INc + c];
    }
    __shared__ float r1[8][32], r2[8][32];
    r1[ty][threadIdx.x] = s1;
    r2[ty][threadIdx.x] = s2;
    __syncthreads();
    if (ty == 0) {
        float t1 = 0.f, t2 = 0.f;
        #pragma unroll
        for (int u = 0; u < 8; ++u) { t1 += r1[u][threadIdx.x]; t2 += r2[u][threadIdx.x]; }
        g_f1[b * Nn + n] = t1 + g_c[0];
        g_f2[b * Nn + n] = t2 + g_c[1];
    }
}

// ---------------- masked softmax rows -> bf16 hi/lo (register-resident) ----------------
__global__ __launch_bounds__(256) void att_kernel(const int* __restrict__ adj) {
    int b = blockIdx.y, i = blockIdx.x;
    int t = threadIdx.x;
    int lane = t & 31, warp = t >> 5;
    float f1v = g_f1[b * Nn + i];
    const int4*   arow = (const int4*)(adj + ((size_t)b * Nn + i) * Nn);
    const float4* f2r  = (const float4*)(g_f2 + b * Nn);
    float4 f2 = f2r[t];
    int4   ad = arow[t];
    float v[4];
    v[0] = f1v + f2.x; v[1] = f1v + f2.y; v[2] = f1v + f2.z; v[3] = f1v + f2.w;
    #pragma unroll
    for (int q = 0; q < 4; ++q) v[q] = v[q] > 0.f ? v[q] : ALPHA * v[q];
    v[0] = (ad.x > 0) ? v[0] : NEGV;
    v[1] = (ad.y > 0) ? v[1] : NEGV;
    v[2] = (ad.z > 0) ? v[2] : NEGV;
    v[3] = (ad.w > 0) ? v[3] : NEGV;

    float m = fmaxf(fmaxf(v[0], v[1]), fmaxf(v[2], v[3]));
    #pragma unroll
    for (int o = 16; o > 0; o >>= 1) m = fmaxf(m, __shfl_xor_sync(0xffffffffu, m, o));
    __shared__ float redm[8], reds[8];
    if (lane == 0) redm[warp] = m;
    __syncthreads();
    m = redm[0];
    #pragma unroll
    for (int u = 1; u < 8; ++u) m = fmaxf(m, redm[u]);

    float p[4], s = 0.f;
    #pragma unroll
    for (int q = 0; q < 4; ++q) { p[q] = __expf(v[q] - m); s += p[q]; }
    #pragma unroll
    for (int o = 16; o > 0; o >>= 1) s += __shfl_xor_sync(0xffffffffu, s, o);
    if (lane == 0) reds[warp] = s;
    __syncthreads();
    s = reds[0];
    #pragma unroll
    for (int u = 1; u < 8; ++u) s += reds[u];
    float inv = 1.f / s;

    bf16 h[4], l[4];
    #pragma unroll
    for (int q = 0; q < 4; ++q) split_bf16(p[q] * inv, h[q], l[q]);
    size_t base = ((size_t)b * Nn + i) * Nn + t * 4;
    *(uint2*)(g_att_h + base) = make_uint2(pack2(h[0], h[1]), pack2(h[2], h[3]));
    *(uint2*)(g_att_l + base) = make_uint2(pack2(l[0], l[1]), pack2(l[2], l[3]));
}

// ---------------- tensor-core GEMMs, cp.async 3-stage, swizzled 32B rows ----------------
// smem per operand-half per stage: 128 rows * 32B = 4 KB; stage stride 4096 B.
// swizzle: 16B chunk c at row r stored at chunk (c ^ ((r>>2)&1)) -> conflict-free
// for both cp.async stores and ldmatrix reads.

// z^T[o][n] = Wcat @ Xcat^T : M=256(o), N=1024(n), K=768, 48 k-steps
__global__ __launch_bounds__(256) void z_mma() {
    const int K = Dd;
    const int NSTEP = Dd / 16;
    int b  = blockIdx.z;
    int m0 = blockIdx.y * 128;
    int n0 = blockIdx.x * 128;
    const bf16* Ah = g_W_h;
    const bf16* Al = g_W_l;
    const bf16* Bh = g_X_h + (size_t)b * Nn * Dd;
    const bf16* Bl = g_X_l + (size_t)b * Nn * Dd;

    __shared__ __align__(16) bf16 sAh[3 * 128 * 16], sAl[3 * 128 * 16];
    __shared__ __align__(16) bf16 sBh[3 * 128 * 16], sBl[3 * 128 * 16];

    int t = threadIdx.x;
    int lrow = t >> 1, lchunk = t & 1;
    uint32_t dsw = (uint32_t)(lrow * 32 + ((lchunk ^ ((lrow >> 2) & 1)) << 4));
    const bf16* gAh = Ah + (size_t)(m0 + lrow) * K + lchunk * 8;
    const bf16* gAl = Al + (size_t)(m0 + lrow) * K + lchunk * 8;
    const bf16* gBh = Bh + (size_t)(n0 + lrow) * K + lchunk * 8;
    const bf16* gBl = Bl + (size_t)(n0 + lrow) * K + lchunk * 8;

    int wid = t >> 5, lane = t & 31;
    int wm0 = (wid >> 2) * 64;
    int wn0 = (wid & 3) * 32;
    int lr = lane & 15;

    uint32_t saAh = (uint32_t)__cvta_generic_to_shared(sAh);
    uint32_t saAl = (uint32_t)__cvta_generic_to_shared(sAl);
    uint32_t saBh = (uint32_t)__cvta_generic_to_shared(sBh);
    uint32_t saBl = (uint32_t)__cvta_generic_to_shared(sBl);
    uint32_t aAddrH[4], aAddrL[4], bAddrH[2], bAddrL[2];
    #pragma unroll
    for (int mb = 0; mb < 4; ++mb) {
        int row = wm0 + mb * 16 + lr;
        uint32_t off = (uint32_t)(row * 32 + (((lane >> 4) ^ ((row >> 2) & 1)) << 4));
        aAddrH[mb] = saAh + off;
        aAddrL[mb] = saAl + off;
    }
    #pragma unroll
    for (int g = 0; g < 2; ++g) {
        int row = wn0 + g * 16 + lr;
        uint32_t off = (uint32_t)(row * 32 + (((lane >> 4) ^ ((row >> 2) & 1)) << 4));
        bAddrH[g] = saBh + off;
        bAddrL[g] = saBl + off;
    }

    float acc[4][4][4];
    #pragma unroll
    for (int i = 0; i < 4; ++i)
        #pragma unroll
        for (int j = 0; j < 4; ++j)
            #pragma unroll
            for (int q = 0; q < 4; ++q) acc[i][j][q] = 0.f;

    // prologue: stages 0 and 1
    cp16(saAh + dsw, gAh); cp16(saAl + dsw, gAl);
    cp16(saBh + dsw, gBh); cp16(saBl + dsw, gBl);
    cp_commit();
    cp16(saAh + 4096 + dsw, gAh + 16); cp16(saAl + 4096 + dsw, gAl + 16);
    cp16(saBh + 4096 + dsw, gBh + 16); cp16(saBl + 4096 + dsw, gBl + 16);
    cp_commit();

    uint32_t Afh[4][4], Afl[4][4], Bfh[2][4], Bfl[2][4];

    for (int i = 0; i < NSTEP; ++i) {
        cp_wait1();
        __syncthreads();
        int nx = i + 2;
        if (nx < NSTEP) {
            uint32_t o = (uint32_t)(nx % 3) * 4096 + dsw;
            int ko = nx * 16;
            cp16(saAh + o, gAh + ko); cp16(saAl + o, gAl + ko);
            cp16(saBh + o, gBh + ko); cp16(saBl + o, gBl + ko);
        }
        cp_commit();
        uint32_t so = (uint32_t)(i % 3) * 4096;
        #pragma unroll
        for (int mb = 0; mb < 4; ++mb) {
            ldsm4(Afh[mb][0], Afh[mb][1], Afh[mb][2], Afh[mb][3], aAddrH[mb] + so);
            ldsm4(Afl[mb][0], Afl[mb][1], Afl[mb][2], Afl[mb][3], aAddrL[mb] + so);
        }
        #pragma unroll
        for (int g = 0; g < 2; ++g) {
            ldsm4(Bfh[g][0], Bfh[g][1], Bfh[g][2], Bfh[g][3], bAddrH[g] + so);
            ldsm4(Bfl[g][0], Bfl[g][1], Bfl[g][2], Bfl[g][3], bAddrL[g] + so);
        }
        #pragma unroll
        for (int mb = 0; mb < 4; ++mb) {
            #pragma unroll
            for (int j = 0; j < 4; ++j) {
                int g = j >> 1, p = j & 1;
                float* C = acc[mb][j];
                mma16816(C[0], C[1], C[2], C[3],
                         Afh[mb][0], Afh[mb][1], Afh[mb][2], Afh[mb][3],
                         Bfh[g][p], Bfh[g][p + 2]);
                mma16816(C[0], C[1], C[2], C[3],
                         Afh[mb][0], Afh[mb][1], Afh[mb][2], Afh[mb][3],
                         Bfl[g][p], Bfl[g][p + 2]);
                mma16816(C[0], C[1], C[2], C[3],
                         Afl[mb][0], Afl[mb][1], Afl[mb][2], Afl[mb][3],
                         Bfh[g][p], Bfh[g][p + 2]);
            }
        }
    }

    int r_lo = lane >> 2, c_off = (lane & 3) * 2;
    size_t base = (size_t)b * OUTc * Nn;
    #pragma unroll
    for (int mb = 0; mb < 4; ++mb) {
        #pragma unroll
        for (int j = 0; j < 4; ++j) {
            int row = m0 + wm0 + mb * 16 + r_lo;
            int col = n0 + wn0 + j * 8 + c_off;
            float* C = acc[mb][j];
            #pragma unroll
            for (int h = 0; h < 2; ++h) {
                int rr = row + h * 8;
                float bz = g_zb[rr];
                float v0 = C[h * 2 + 0] + bz;
                float v1 = C[h * 2 + 1] + bz;
                bf16 h0, l0, h1, l1;
                split_bf16(v0, h0, l0);
                split_bf16(v1, h1, l1);
                size_t idx = base + (size_t)rr * Nn + col;
                *(uint32_t*)(g_z_h + idx) = pack2(h0, h1);
                *(uint32_t*)(g_z_l + idx) = pack2(l0, l1);
            }
        }
    }
}

// out[i][o] = elu(att @ z^T + fc_b) : M=1024(i), N=256(o), K=1024, 64 k-steps
__global__ __launch_bounds__(256) void out_mma(const float* __restrict__ bias,
                                               float* __restrict__ outF) {
    const int K = Nn;
    const int NSTEP = Nn / 16;
    int b  = blockIdx.z;
    int m0 = blockIdx.y * 128;
    int n0 = blockIdx.x * 128;
    const bf16* Ah = g_att_h + (size_t)b * Nn * Nn;
    const bf16* Al = g_att_l + (size_t)b * Nn * Nn;
    const bf16* Bh = g_z_h + (size_t)b * OUTc * Nn;
    const bf16* Bl = g_z_l + (size_t)b * OUTc * Nn;

    __shared__ __align__(16) bf16 sAh[3 * 128 * 16], sAl[3 * 128 * 16];
    __shared__ __align__(16) bf16 sBh[3 * 128 * 16], sBl[3 * 128 * 16];

    int t = threadIdx.x;
    int lrow = t >> 1, lchunk = t & 1;
    uint32_t dsw = (uint32_t)(lrow * 32 + ((lchunk ^ ((lrow >> 2) & 1)) << 4));
    const bf16* gAh = Ah + (size_t)(m0 + lrow) * K + lchunk * 8;
    const bf16* gAl = Al + (size_t)(m0 + lrow) * K + lchunk * 8;
    const bf16* gBh = Bh + (size_t)(n0 + lrow) * K + lchunk * 8;
    const bf16* gBl = Bl + (size_t)(n0 + lrow) * K + lchunk * 8;

    int wid = t >> 5, lane = t & 31;
    int wm0 = (wid >> 2) * 64;
    int wn0 = (wid & 3) * 32;
    int lr = lane & 15;

    uint32_t saAh = (uint32_t)__cvta_generic_to_shared(sAh);
    uint32_t saAl = (uint32_t)__cvta_generic_to_shared(sAl);
    uint32_t saBh = (uint32_t)__cvta_generic_to_shared(sBh);
    uint32_t saBl = (uint32_t)__cvta_generic_to_shared(sBl);
    uint32_t aAddrH[4], aAddrL[4], bAddrH[2], bAddrL[2];
    #pragma unroll
    for (int mb = 0; mb < 4; ++mb) {
        int row = wm0 + mb * 16 + lr;
        uint32_t off = (uint32_t)(row * 32 + (((lane >> 4) ^ ((row >> 2) & 1)) << 4));
        aAddrH[mb] = saAh + off;
        aAddrL[mb] = saAl + off;
    }
    #pragma unroll
    for (int g = 0; g < 2; ++g) {
        int row = wn0 + g * 16 + lr;
        uint32_t off = (uint32_t)(row * 32 + (((lane >> 4) ^ ((row >> 2) & 1)) << 4));
        bAddrH[g] = saBh + off;
        bAddrL[g] = saBl + off;
    }

    float acc[4][4][4];
    #pragma unroll
    for (int i = 0; i < 4; ++i)
        #pragma unroll
        for (int j = 0; j < 4; ++j)
            #pragma unroll
            for (int q = 0; q < 4; ++q) acc[i][j][q] = 0.f;

    cp16(saAh + dsw, gAh); cp16(saAl + dsw, gAl);
    cp16(saBh + dsw, gBh); cp16(saBl + dsw, gBl);
    cp_commit();
    cp16(saAh + 4096 + dsw, gAh + 16); cp16(saAl + 4096 + dsw, gAl + 16);
    cp16(saBh + 4096 + dsw, gBh + 16); cp16(saBl + 4096 + dsw, gBl + 16);
    cp_commit();

    uint32_t Afh[4][4], Afl[4][4], Bfh[2][4], Bfl[2][4];

    for (int i = 0; i < NSTEP; ++i) {
        cp_wait1();
        __syncthreads();
        int nx = i + 2;
        if (nx < NSTEP) {
            uint32_t o = (uint32_t)(nx % 3) * 4096 + dsw;
            int ko = nx * 16;
            cp16(saAh + o, gAh + ko); cp16(saAl + o, gAl + ko);
            cp16(saBh + o, gBh + ko); cp16(saBl + o, gBl + ko);
        }
        cp_commit();
        uint32_t so = (uint32_t)(i % 3) * 4096;
        #pragma unroll
        for (int mb = 0; mb < 4; ++mb) {
            ldsm4(Afh[mb][0], Afh[mb][1], Afh[mb][2], Afh[mb][3], aAddrH[mb] + so);
            ldsm4(Afl[mb][0], Afl[mb][1], Afl[mb][2], Afl[mb][3], aAddrL[mb] + so);
        }
        #pragma unroll
        for (int g = 0; g < 2; ++g) {
            ldsm4(Bfh[g][0], Bfh[g][1], Bfh[g][2], Bfh[g][3], bAddrH[g] + so);
            ldsm4(Bfl[g][0], Bfl[g][1], Bfl[g][2], Bfl[g][3], bAddrL[g] + so);
        }
        #pragma unroll
        for (int mb = 0; mb < 4; ++mb) {
            #pragma unroll
            for (int j = 0; j < 4; ++j) {
                int g = j >> 1, p = j & 1;
                float* C = acc[mb][j];
                mma16816(C[0], C[1], C[2], C[3],
                         Afh[mb][0], Afh[mb][1], Afh[mb][2], Afh[mb][3],
                         Bfh[g][p], Bfh[g][p + 2]);
                mma16816(C[0], C[1], C[2], C[3],
                         Afh[mb][0], Afh[mb][1], Afh[mb][2], Afh[mb][3],
                         Bfl[g][p], Bfl[g][p + 2]);
                mma16816(C[0], C[1], C[2], C[3],
                         Afl[mb][0], Afl[mb][1], Afl[mb][2], Afl[mb][3],
                         Bfh[g][p], Bfh[g][p + 2]);
            }
        }
    }

    int r_lo = lane >> 2, c_off = (lane & 3) * 2;
    size_t base = (size_t)b * Nn * OUTc;
    #pragma unroll
    for (int mb = 0; mb < 4; ++mb) {
        #pragma unroll
        for (int j = 0; j < 4; ++j) {
            int row = m0 + wm0 + mb * 16 + r_lo;
            int col = n0 + wn0 + j * 8 + c_off;
            float* C = acc[mb][j];
            #pragma unroll
            for (int h = 0; h < 2; ++h) {
                int rr = row + h * 8;
                float v0 = C[h * 2 + 0] + bias[col + 0];
                float v1 = C[h * 2 + 1] + bias[col + 1];
                v0 = v0 > 0.f ? v0 : (__expf(v0) - 1.f);
                v1 = v1 > 0.f ? v1 : (__expf(v1) - 1.f);
                *(float2*)(outF + base + (size_t)rr * OUTc + col) = make_float2(v0, v1);
            }
        }
    }
}

extern "C" void kernel_launch(void* const* d_in, const int* in_sizes, int n_in,
                              void* d_out, int out_size) {
    const float* x    = (const float*)d_in[0];
    const float* ax   = (const float*)d_in[1];
    const int*   adj  = (const int*)d_in[2];
    const float* WQ_w = (const float*)d_in[3];
    const float* WQ_b = (const float*)d_in[4];
    const float* a    = (const float*)d_in[5];
    const float* fc_w = (const float*)d_in[6];
    const float* fc_b = (const float*)d_in[7];
    float* out = (float*)d_out;

    prep_M<<<256, 256>>>(fc_w, WQ_w);
    prep_small<<<1, 256>>>(WQ_w, WQ_b, a, fc_w);
    conv_w<<<(OUTc * Dd) / 256, 256>>>(fc_w);

    dim3 cxg(Dd / 32, Nn / 32, Bb);
    conv_x<<<cxg, 256>>>(x, ax);

    dim3 fg(Nn / 32, Bb), fb(32, 8);
    f_kernel<<<fg, fb>>>(x, ax, a);

    dim3 ag(Nn, Bb);
    att_kernel<<<ag, 256>>>(adj);

    z_mma<<<dim3(Nn / 128, OUTc / 128, Bb), 256>>>();
    out_mma<<<dim3(OUTc / 128, Nn / 128, Bb), 256>>>(fc_b, out);
}